// round 3
// baseline (speedup 1.0000x reference)
#include <cuda_runtime.h>
#include <math.h>

#define NMODES 64
#define LSEQ   262144
#define SEG    64
#define NSEGS  (LSEQ/SEG)        /* 4096 */
#define CPT    4                 /* segments composed per scan thread */
#define SCAN_T (NSEGS/CPT)       /* 1024 */
#define TILE   128
#define NTILES (LSEQ/TILE)       /* 2048 */
#define SEGS_PER_TILE (TILE/SEG) /* 2 */

// ---------------- scratch (static device globals; no allocation) ----------------
__device__ float2  g_P[NMODES * NSEGS];      // per-segment partial states, [n][seg]
__device__ float2  g_carry[NMODES * NSEGS];  // carry-in state per segment, [n][seg]
__device__ float2  g_z[NMODES];              // z_n = exp(dt*A_n)
__device__ float2  g_coeff[NMODES];          // C_n * (z_n - 1) / A_n
__device__ double2 g_a64[NMODES];            // z_n^64
__device__ double2 g_mk[NMODES * 10];        // z_n^(256 * 2^k), k = 0..9

static __device__ __forceinline__ double2 cexp_d(double re, double im) {
    double m = exp(re);
    double s, c;
    sincos(im, &s, &c);
    return make_double2(m * c, m * s);
}

// ---------------- K0: per-mode constants (double precision phases) ----------------
__global__ void k0_setup(const float* __restrict__ A_re,
                         const float* __restrict__ A_im,
                         const float* __restrict__ C,
                         const float* __restrict__ log_step) {
    int n = threadIdx.x;
    if (n >= NMODES) return;
    double dt = exp((double)log_step[0]);
    double ar = (double)A_re[n];
    double ai = (double)A_im[n];
    double dr = dt * ar, di = dt * ai;     // dt*A

    double2 z = cexp_d(dr, di);
    g_z[n] = make_float2((float)z.x, (float)z.y);

    // coeff = Ct * (z - 1) / A,   Ct = C[n,0] + i*C[n,1]
    double ctr = (double)C[2 * n], cti = (double)C[2 * n + 1];
    double wr = z.x - 1.0, wi = z.y;
    double den = ar * ar + ai * ai;
    double qr = (wr * ar + wi * ai) / den;
    double qi = (wi * ar - wr * ai) / den;
    g_coeff[n] = make_float2((float)(ctr * qr - cti * qi),
                             (float)(ctr * qi + cti * qr));

    g_a64[n] = cexp_d(64.0 * dr, 64.0 * di);

    double sc = 256.0;
    for (int k = 0; k < 10; k++) {
        g_mk[n * 10 + k] = cexp_d(sc * dr, sc * di);
        sc *= 2.0;
    }
}

// ---------------- K1: per-segment partial states (zero initial condition) ----------------
// grid = LSEQ/256 blocks, 256 threads: 64 modes x 4 segments per block.
__global__ void k1_partials(const float* __restrict__ u) {
    __shared__ float  su[256];
    __shared__ float2 sp[256];
    int tid  = threadIdx.x;
    int tile = blockIdx.x;
    su[tid] = u[tile * 256 + tid];
    int n = tid & 63, s = tid >> 6;        // s in 0..3
    float2 z = g_z[n];
    __syncthreads();

    float2 P = make_float2(0.f, 0.f);
    const float* up = su + s * SEG;
#pragma unroll
    for (int j = 0; j < SEG; j++) {
        float uv = up[j];
        float pr = fmaf(z.x, P.x, fmaf(-z.y, P.y, uv));
        float pi = fmaf(z.x, P.y, z.y * P.x);
        P.x = pr; P.y = pi;
    }
    sp[s * 64 + n] = P;
    __syncthreads();

    // transpose write-out: [n][seg] layout, 32B-contiguous groups of 4 segs
    int n2 = tid >> 2, s2 = tid & 3;
    g_P[n2 * NSEGS + tile * 4 + s2] = sp[s2 * 64 + n2];
}

// ---------------- K2: Kogge-Stone scan across segments (per mode), emit carries ----------------
// grid = NMODES blocks, SCAN_T threads. States in double.
__global__ void k2_scan() {
    __shared__ double2 sB[SCAN_T];
    int n = blockIdx.x;
    int i = threadIdx.x;
    double2 a64 = g_a64[n];

    float2 Pl[CPT];
    const float2* pp = g_P + n * NSEGS + i * CPT;
#pragma unroll
    for (int j = 0; j < CPT; j++) Pl[j] = pp[j];

    // compose CPT segments into one scan element
    double Br = 0.0, Bi = 0.0;
#pragma unroll
    for (int j = 0; j < CPT; j++) {
        double tr = a64.x * Br - a64.y * Bi + (double)Pl[j].x;
        double ti = a64.x * Bi + a64.y * Br + (double)Pl[j].y;
        Br = tr; Bi = ti;
    }
    sB[i] = make_double2(Br, Bi);

    // inclusive Kogge-Stone: B[i] = m^(off) * B[i-off] + B[i]
    int k = 0;
    for (int off = 1; off < SCAN_T; off <<= 1, k++) {
        double2 m = g_mk[n * 10 + k];
        __syncthreads();
        double lr = 0.0, li = 0.0;
        if (i >= off) { double2 t = sB[i - off]; lr = t.x; li = t.y; }
        __syncthreads();
        if (i >= off) {
            double nr = m.x * lr - m.y * li + Br;
            double ni = m.x * li + m.y * lr + Bi;
            Br = nr; Bi = ni;
            sB[i] = make_double2(Br, Bi);
        }
    }
    __syncthreads();

    // exclusive prefix -> per-segment carry-ins
    double Er = 0.0, Ei = 0.0;
    if (i > 0) { double2 t = sB[i - 1]; Er = t.x; Ei = t.y; }
    float2* cp = g_carry + n * NSEGS + i * CPT;
#pragma unroll
    for (int j = 0; j < CPT; j++) {
        cp[j] = make_float2((float)Er, (float)Ei);
        double tr = a64.x * Er - a64.y * Ei + (double)Pl[j].x;
        double ti = a64.x * Ei + a64.y * Er + (double)Pl[j].y;
        Er = tr; Ei = ti;
    }
}

// ---------------- K3: replay with carries, reduce over modes, write y ----------------
// grid = NTILES blocks, TILE threads: 64 modes x SEGS_PER_TILE segments per block.
__global__ void k3_apply(const float* __restrict__ u,
                         const float* __restrict__ D,
                         float* __restrict__ y) {
    __shared__ float su[TILE];
    __shared__ float contrib[NMODES][TILE + 1];  // +1 pad: conflict-free
    int tid  = threadIdx.x;
    int tile = blockIdx.x;
    su[tid] = u[tile * TILE + tid];
    int n = tid & 63, s = tid >> 6;              // s in 0..SEGS_PER_TILE-1
    int seg = tile * SEGS_PER_TILE + s;
    float2 z  = g_z[n];
    float2 cf = g_coeff[n];
    float2 x  = g_carry[n * NSEGS + seg];
    __syncthreads();

    const float* up   = su + s * SEG;
    float*       crow = &contrib[n][s * SEG];
#pragma unroll
    for (int j = 0; j < SEG; j++) {
        float uv = up[j];
        float xr = fmaf(z.x, x.x, fmaf(-z.y, x.y, uv));
        float xi = fmaf(z.x, x.y, z.y * x.x);
        x.x = xr; x.y = xi;
        crow[j] = fmaf(cf.x, xr, -cf.y * xi);
    }
    __syncthreads();

    float acc0 = 0.f, acc1 = 0.f, acc2 = 0.f, acc3 = 0.f;
#pragma unroll
    for (int nn = 0; nn < NMODES; nn += 4) {
        acc0 += contrib[nn + 0][tid];
        acc1 += contrib[nn + 1][tid];
        acc2 += contrib[nn + 2][tid];
        acc3 += contrib[nn + 3][tid];
    }
    float acc = (acc0 + acc1) + (acc2 + acc3);
    y[tile * TILE + tid] = fmaf(D[0], su[tid], acc);
}

// ---------------- host ----------------
extern "C" void kernel_launch(void* const* d_in, const int* in_sizes, int n_in,
                              void* d_out, int out_size) {
    // robust input identification by size (dict order preserved for ties)
    const float* u = 0; const float* A_re = 0; const float* A_im = 0;
    const float* C = 0; const float* D = 0; const float* log_step = 0;
    for (int i = 0; i < n_in; i++) {
        int sz = in_sizes[i];
        const float* p = (const float*)d_in[i];
        if (sz == LSEQ)            { if (!u) u = p; }
        else if (sz == 2 * NMODES) { if (!C) C = p; }
        else if (sz == NMODES)     { if (!A_re) A_re = p; else A_im = p; }
        else if (sz == 1)          { if (!D) D = p; else log_step = p; }
    }
    float* y = (float*)d_out;

    k0_setup<<<1, NMODES>>>(A_re, A_im, C, log_step);
    k1_partials<<<LSEQ / 256, 256>>>(u);
    k2_scan<<<NMODES, SCAN_T>>>();
    k3_apply<<<NTILES, TILE>>>(u, D, y);
}

// round 5
// speedup vs baseline: 2.3003x; 2.3003x over previous
#include <cuda_runtime.h>
#include <math.h>

#define NMODES 64
#define LSEQ   262144
#define SEG    64
#define NSEGS  (LSEQ/SEG)        /* 4096 */
#define CPT    16                /* segments composed per scan thread */
#define SCAN_T (NSEGS/CPT)       /* 256 */
#define K1_TILE 1024
#define K1_BLOCKS (LSEQ/K1_TILE) /* 256 */
#define K3_TILE 256
#define K3_BLOCKS (LSEQ/K3_TILE) /* 1024 */

typedef unsigned long long u64t;

// ---------------- f32x2 packed helpers (FFMA2 path, PTX-only) ----------------
__device__ __forceinline__ u64t pk2(float lo, float hi) {
    u64t r; asm("mov.b64 %0,{%1,%2};" : "=l"(r) : "f"(lo), "f"(hi)); return r;
}
__device__ __forceinline__ void upk2(float& lo, float& hi, u64t v) {
    asm("mov.b64 {%0,%1},%2;" : "=f"(lo), "=f"(hi) : "l"(v));
}
#define FMA2(d,a,b,c) asm("fma.rn.f32x2 %0,%1,%2,%3;" : "=l"(d) : "l"(a), "l"(b), "l"(c))
#define MUL2(d,a,b)   asm("mul.rn.f32x2 %0,%1,%2;"    : "=l"(d) : "l"(a), "l"(b))
#define ADD2(d,a,b)   asm("add.rn.f32x2 %0,%1,%2;"    : "=l"(d) : "l"(a), "l"(b))

// ---------------- scratch (static device globals; no allocation) ----------------
__device__ float4 g_P4[NMODES * NSEGS / 2];      // per-segment partials [n][seg], float2 pairs
__device__ float4 g_carry4[NMODES * NSEGS / 2];  // carry-in per segment [n][seg]
__device__ float2 g_z[NMODES];                   // z_n = exp(dt*A_n)
__device__ float2 g_cf[NMODES];                  // C_n * (z_n - 1) / A_n
__device__ float2 g_a64f[NMODES];                // z^64
__device__ float2 g_mkf[NMODES * 8];             // z^(1024 * 2^k), k=0..7

static __device__ __forceinline__ double2 cexp_d(double re, double im) {
    double m = exp(re); double s, c; sincos(im, &s, &c);
    return make_double2(m * c, m * s);
}
static __device__ __forceinline__ double2 csq(double2 w) {
    return make_double2(w.x * w.x - w.y * w.y, 2.0 * w.x * w.y);
}

// ---------------- K0: constants via 1 cexp + squaring chain ----------------
__global__ void k0_setup(const float* __restrict__ A_re,
                         const float* __restrict__ A_im,
                         const float* __restrict__ C,
                         const float* __restrict__ log_step) {
    int n = threadIdx.x;
    if (n >= NMODES) return;
    double dt = exp((double)log_step[0]);
    double ar = (double)A_re[n], ai = (double)A_im[n];
    double dr = dt * ar, di = dt * ai;

    double2 z = cexp_d(dr, di);
    g_z[n] = make_float2((float)z.x, (float)z.y);

    // coeff = Ct * (z - 1) / A
    double ctr = (double)C[2 * n], cti = (double)C[2 * n + 1];
    double wr = z.x - 1.0, wi = z.y;
    double den = ar * ar + ai * ai;
    double qr = (wr * ar + wi * ai) / den;
    double qi = (wi * ar - wr * ai) / den;
    g_cf[n] = make_float2((float)(ctr * qr - cti * qi),
                          (float)(ctr * qi + cti * qr));

    double2 w = z;
    for (int k = 0; k < 6; k++) w = csq(w);          // z^64
    g_a64f[n] = make_float2((float)w.x, (float)w.y);
    for (int k = 0; k < 4; k++) w = csq(w);          // z^1024
    for (int k = 0; k < 8; k++) {                    // z^(1024*2^k)
        g_mkf[n * 8 + k] = make_float2((float)w.x, (float)w.y);
        w = csq(w);
    }
}

// ---------------- K1: per-segment partials, 4 modes/thread via f32x2 ----------------
// grid = 256 blocks x 256 threads. Block covers 1024 samples (16 segs).
// thread: q = t&15 (mode group), s = t>>4 (seg). Chains: (q,q+16) and (q+32,q+48).
__global__ void k1_partials(const float* __restrict__ u) {
    __shared__ float su[K1_TILE];
    int t = threadIdx.x, tile = blockIdx.x;
    ((float4*)su)[t] = ((const float4*)u)[tile * 256 + t];
    int q = t & 15, s = t >> 4;

    float2 za = g_z[q],      zb = g_z[q + 16];
    float2 zc = g_z[q + 32], zd = g_z[q + 48];
    u64t zr0 = pk2(za.x, zb.x), zi0 = pk2(za.y, zb.y), nzi0 = pk2(-za.y, -zb.y);
    u64t zr1 = pk2(zc.x, zd.x), zi1 = pk2(zc.y, zd.y), nzi1 = pk2(-zc.y, -zd.y);
    __syncthreads();

    u64t Pr0 = 0, Pi0 = 0, Pr1 = 0, Pi1 = 0;   // bit pattern {0.f,0.f}
    const float* up = su + s * SEG;
#pragma unroll
    for (int j = 0; j < SEG; j++) {
        float uv = up[j];
        u64t u2 = pk2(uv, uv);
        u64t t0, v0, t1, v1;
        FMA2(t0, nzi0, Pi0, u2); MUL2(v0, zi0, Pr0);
        FMA2(Pr0, zr0, Pr0, t0); FMA2(Pi0, zr0, Pi0, v0);
        FMA2(t1, nzi1, Pi1, u2); MUL2(v1, zi1, Pr1);
        FMA2(Pr1, zr1, Pr1, t1); FMA2(Pi1, zr1, Pi1, v1);
    }

    int seg = tile * 16 + s;
    float2* gP = (float2*)g_P4;
    float ra, rb, ia, ib;
    upk2(ra, rb, Pr0); upk2(ia, ib, Pi0);
    gP[q * NSEGS + seg]        = make_float2(ra, ia);
    gP[(q + 16) * NSEGS + seg] = make_float2(rb, ib);
    upk2(ra, rb, Pr1); upk2(ia, ib, Pi1);
    gP[(q + 32) * NSEGS + seg] = make_float2(ra, ia);
    gP[(q + 48) * NSEGS + seg] = make_float2(rb, ib);
}

// ---------------- K2: fp32 Kogge-Stone scan, emit carries ----------------
// grid = NMODES blocks x SCAN_T(=256) threads.
__global__ void k2_scan() {
    __shared__ float2 sB[SCAN_T];
    int n = blockIdx.x, i = threadIdx.x;
    float2 a = g_a64f[n];

    float2 P[CPT];
    const float4* pp = g_P4 + (n * NSEGS) / 2 + i * (CPT / 2);
#pragma unroll
    for (int j = 0; j < CPT / 2; j++) {
        float4 v = pp[j];
        P[2 * j]     = make_float2(v.x, v.y);
        P[2 * j + 1] = make_float2(v.z, v.w);
    }

    float Br = 0.f, Bi = 0.f;
#pragma unroll
    for (int j = 0; j < CPT; j++) {
        float tr = fmaf(-a.y, Bi, P[j].x);
        float ti = fmaf( a.y, Br, P[j].y);
        Br = fmaf(a.x, Br, tr);
        Bi = fmaf(a.x, Bi, ti);
    }
    sB[i] = make_float2(Br, Bi);

#pragma unroll
    for (int k = 0; k < 8; k++) {
        int off = 1 << k;
        float2 m = g_mkf[n * 8 + k];
        __syncthreads();
        float lr = 0.f, li = 0.f;
        if (i >= off) { float2 tt = sB[i - off]; lr = tt.x; li = tt.y; }
        __syncthreads();
        if (i >= off) {
            float nr = fmaf(m.x, lr, fmaf(-m.y, li, Br));
            float ni = fmaf(m.x, li, fmaf( m.y, lr, Bi));
            Br = nr; Bi = ni;
            sB[i] = make_float2(Br, Bi);
        }
    }
    __syncthreads();

    float Er = 0.f, Ei = 0.f;
    if (i > 0) { float2 tt = sB[i - 1]; Er = tt.x; Ei = tt.y; }
    float4* cp = g_carry4 + (n * NSEGS) / 2 + i * (CPT / 2);
#pragma unroll
    for (int j = 0; j < CPT / 2; j++) {
        float4 o;
        o.x = Er; o.y = Ei;
        {
            float tr = fmaf(-a.y, Ei, P[2 * j].x);
            float ti = fmaf( a.y, Er, P[2 * j].y);
            Er = fmaf(a.x, Er, tr); Ei = fmaf(a.x, Ei, ti);
        }
        o.z = Er; o.w = Ei;
        {
            float tr = fmaf(-a.y, Ei, P[2 * j + 1].x);
            float ti = fmaf( a.y, Er, P[2 * j + 1].y);
            Er = fmaf(a.x, Er, tr); Ei = fmaf(a.x, Ei, ti);
        }
        cp[j] = o;
    }
}

// ---------------- K3: replay + output, 4 modes/thread via f32x2 ----------------
// grid = 1024 blocks x 64 threads. Block covers 256 samples (4 segs).
// q = t&15, s = t>>4 (0..3). contrib packed: 16 rows of float2 (lane-sum deferred).
__global__ void k3_apply(const float* __restrict__ u,
                         const float* __restrict__ D,
                         float* __restrict__ y) {
    __shared__ float su[K3_TILE];
    __shared__ float2 ctb[16][K3_TILE + 1];
    int t = threadIdx.x, tile = blockIdx.x;
    ((float4*)su)[t] = ((const float4*)u)[tile * 64 + t];
    int q = t & 15, s = t >> 4;
    int seg = tile * 4 + s;

    float2 za = g_z[q],      zb = g_z[q + 16];
    float2 zc = g_z[q + 32], zd = g_z[q + 48];
    u64t zr0 = pk2(za.x, zb.x), zi0 = pk2(za.y, zb.y), nzi0 = pk2(-za.y, -zb.y);
    u64t zr1 = pk2(zc.x, zd.x), zi1 = pk2(zc.y, zd.y), nzi1 = pk2(-zc.y, -zd.y);
    float2 ca = g_cf[q],      cb = g_cf[q + 16];
    float2 cc = g_cf[q + 32], cd = g_cf[q + 48];
    u64t cr0 = pk2(ca.x, cb.x), nci0 = pk2(-ca.y, -cb.y);
    u64t cr1 = pk2(cc.x, cd.x), nci1 = pk2(-cc.y, -cd.y);

    const float2* gc = (const float2*)g_carry4;
    float2 xa = gc[q * NSEGS + seg],        xb = gc[(q + 16) * NSEGS + seg];
    float2 xc = gc[(q + 32) * NSEGS + seg], xd = gc[(q + 48) * NSEGS + seg];
    u64t Pr0 = pk2(xa.x, xb.x), Pi0 = pk2(xa.y, xb.y);
    u64t Pr1 = pk2(xc.x, xd.x), Pi1 = pk2(xc.y, xd.y);
    __syncthreads();

    const float* up = su + s * SEG;
    u64t* crow = (u64t*)&ctb[q][s * SEG];
#pragma unroll
    for (int j = 0; j < SEG; j++) {
        float uv = up[j];
        u64t u2 = pk2(uv, uv);
        u64t t0, v0, t1, v1, c0, c1, cs;
        FMA2(t0, nzi0, Pi0, u2); MUL2(v0, zi0, Pr0);
        FMA2(Pr0, zr0, Pr0, t0); FMA2(Pi0, zr0, Pi0, v0);
        FMA2(t1, nzi1, Pi1, u2); MUL2(v1, zi1, Pr1);
        FMA2(Pr1, zr1, Pr1, t1); FMA2(Pi1, zr1, Pi1, v1);
        MUL2(c0, nci0, Pi0); FMA2(c0, cr0, Pr0, c0);
        MUL2(c1, nci1, Pi1); FMA2(c1, cr1, Pr1, c1);
        ADD2(cs, c0, c1);
        crow[j] = cs;
    }
    __syncthreads();

    float Dv = D[0];
#pragma unroll
    for (int k = 0; k < 4; k++) {
        int col = t + k * 64;                 // interleaved: 2-way conflicts max
        u64t acc = *(const u64t*)&ctb[0][col];
#pragma unroll
        for (int r = 1; r < 16; r++) {
            u64t v2 = *(const u64t*)&ctb[r][col];
            ADD2(acc, acc, v2);
        }
        float lo, hi; upk2(lo, hi, acc);
        y[tile * K3_TILE + col] = fmaf(Dv, su[col], lo + hi);
    }
}

// ---------------- host ----------------
extern "C" void kernel_launch(void* const* d_in, const int* in_sizes, int n_in,
                              void* d_out, int out_size) {
    const float* u = 0; const float* A_re = 0; const float* A_im = 0;
    const float* C = 0; const float* D = 0; const float* log_step = 0;
    for (int i = 0; i < n_in; i++) {
        int sz = in_sizes[i];
        const float* p = (const float*)d_in[i];
        if (sz == LSEQ)            { if (!u) u = p; }
        else if (sz == 2 * NMODES) { if (!C) C = p; }
        else if (sz == NMODES)     { if (!A_re) A_re = p; else A_im = p; }
        else if (sz == 1)          { if (!D) D = p; else log_step = p; }
    }
    float* y = (float*)d_out;

    k0_setup<<<1, NMODES>>>(A_re, A_im, C, log_step);
    k1_partials<<<K1_BLOCKS, 256>>>(u);
    k2_scan<<<NMODES, SCAN_T>>>();
    k3_apply<<<K3_BLOCKS, 64>>>(u, D, y);
}

// round 6
// speedup vs baseline: 2.4513x; 1.0656x over previous
#include <cuda_runtime.h>
#include <math.h>

#define NMODES 64
#define LSEQ   262144
#define SEG    64
#define NSEGS  (LSEQ/SEG)        /* 4096 */
#define CPT    16                /* segments composed per scan thread */
#define SCAN_T (NSEGS/CPT)       /* 256 */
#define K1_TILE 2048
#define K1_THR  512
#define K1_BLOCKS (LSEQ/K1_TILE) /* 128 */
#define K3_TILE 512
#define K3_THR  128
#define K3_BLOCKS (LSEQ/K3_TILE) /* 512 */
#define CTB_STRIDE 513           /* %32==1: conflict-light */

typedef unsigned long long u64t;

// ---------------- f32x2 packed helpers (FFMA2 path, PTX-only) ----------------
__device__ __forceinline__ u64t pk2(float lo, float hi) {
    u64t r; asm("mov.b64 %0,{%1,%2};" : "=l"(r) : "f"(lo), "f"(hi)); return r;
}
__device__ __forceinline__ void upk2(float& lo, float& hi, u64t v) {
    asm("mov.b64 {%0,%1},%2;" : "=f"(lo), "=f"(hi) : "l"(v));
}
#define FMA2(d,a,b,c) asm("fma.rn.f32x2 %0,%1,%2,%3;" : "=l"(d) : "l"(a), "l"(b), "l"(c))
#define MUL2(d,a,b)   asm("mul.rn.f32x2 %0,%1,%2;"    : "=l"(d) : "l"(a), "l"(b))
#define ADD2(d,a,b)   asm("add.rn.f32x2 %0,%1,%2;"    : "=l"(d) : "l"(a), "l"(b))

// ---------------- scratch (static device globals; no allocation) ----------------
__device__ float4 g_P4[NMODES * NSEGS / 2];      // per-segment partials [n][seg]
__device__ float4 g_carry4[NMODES * NSEGS / 2];  // carry-in per segment [n][seg]
__device__ float2 g_z[NMODES];                   // z_n = exp(dt*A_n)
__device__ float2 g_cf[NMODES];                  // C_n * (z_n - 1) / A_n
__device__ float2 g_a64f[NMODES];                // z^64
__device__ float2 g_mkf[NMODES * 8];             // z^(1024 * 2^k), k=0..7

// ---------------- fast z^e: double phase reduction + MUFU sin/cos ----------------
static __device__ __forceinline__ float2 cexp_pow(double dr, double di, double e) {
    float m = expf((float)(e * dr));
    double t = e * di;
    double q = rint(t * 0.15915494309189533576888376337251);   // 1/(2*pi)
    double r = fma(q, -6.283185307179586476925286766559, t);   // t mod 2*pi
    float s, c;
    sincosf((float)r, &s, &c);
    return make_float2(m * c, m * s);
}

// ---------------- K0: per-mode constants ----------------
__global__ void k0_setup(const float* __restrict__ A_re,
                         const float* __restrict__ A_im,
                         const float* __restrict__ C,
                         const float* __restrict__ log_step) {
    int n = threadIdx.x;
    if (n >= NMODES) return;
    double dt = exp((double)log_step[0]);
    double ar = (double)A_re[n], ai = (double)A_im[n];
    double dr = dt * ar, di = dt * ai;

    float2 z = cexp_pow(dr, di, 1.0);
    g_z[n] = z;

    // coeff = Ct * (z - 1) / A
    double ctr = (double)C[2 * n], cti = (double)C[2 * n + 1];
    double wr = (double)z.x - 1.0, wi = (double)z.y;
    double den = ar * ar + ai * ai;
    double qr = (wr * ar + wi * ai) / den;
    double qi = (wi * ar - wr * ai) / den;
    g_cf[n] = make_float2((float)(ctr * qr - cti * qi),
                          (float)(ctr * qi + cti * qr));

    g_a64f[n] = cexp_pow(dr, di, 64.0);
    double e = 1024.0;
#pragma unroll
    for (int k = 0; k < 8; k++) {
        g_mkf[n * 8 + k] = cexp_pow(dr, di, e);
        e *= 2.0;
    }
}

// ---------------- K1: per-segment partials, 4 modes/thread via f32x2 ----------------
// grid = 128 blocks x 512 threads. Block covers 2048 samples (32 segs).
// q = t&15 (mode group), s = t>>4 (seg 0..31). Chains: (q,q+16) and (q+32,q+48).
__global__ void k1_partials(const float* __restrict__ u) {
    __shared__ float su[K1_TILE];
    int t = threadIdx.x, tile = blockIdx.x;
    ((float4*)su)[t] = ((const float4*)u)[tile * (K1_TILE / 4) + t];
    int q = t & 15, s = t >> 4;

    float2 za = g_z[q],      zb = g_z[q + 16];
    float2 zc = g_z[q + 32], zd = g_z[q + 48];
    u64t zr0 = pk2(za.x, zb.x), zi0 = pk2(za.y, zb.y), nzi0 = pk2(-za.y, -zb.y);
    u64t zr1 = pk2(zc.x, zd.x), zi1 = pk2(zc.y, zd.y), nzi1 = pk2(-zc.y, -zd.y);
    __syncthreads();

    u64t Pr0 = 0, Pi0 = 0, Pr1 = 0, Pi1 = 0;   // bit pattern {0.f,0.f}
    const float* up = su + s * SEG;
#pragma unroll
    for (int j = 0; j < SEG; j++) {
        float uv = up[j];
        u64t u2 = pk2(uv, uv);
        u64t t0, v0, t1, v1;
        FMA2(t0, nzi0, Pi0, u2); MUL2(v0, zi0, Pr0);
        FMA2(Pr0, zr0, Pr0, t0); FMA2(Pi0, zr0, Pi0, v0);
        FMA2(t1, nzi1, Pi1, u2); MUL2(v1, zi1, Pr1);
        FMA2(Pr1, zr1, Pr1, t1); FMA2(Pi1, zr1, Pi1, v1);
    }

    int seg = tile * 32 + s;
    float2* gP = (float2*)g_P4;
    float ra, rb, ia, ib;
    upk2(ra, rb, Pr0); upk2(ia, ib, Pi0);
    gP[q * NSEGS + seg]        = make_float2(ra, ia);
    gP[(q + 16) * NSEGS + seg] = make_float2(rb, ib);
    upk2(ra, rb, Pr1); upk2(ia, ib, Pi1);
    gP[(q + 32) * NSEGS + seg] = make_float2(ra, ia);
    gP[(q + 48) * NSEGS + seg] = make_float2(rb, ib);
}

// ---------------- K2: fp32 Kogge-Stone scan, emit carries ----------------
// grid = NMODES blocks x SCAN_T(=256) threads.
__global__ void k2_scan() {
    __shared__ float2 sB[SCAN_T];
    int n = blockIdx.x, i = threadIdx.x;
    float2 a = g_a64f[n];

    float2 P[CPT];
    const float4* pp = g_P4 + (n * NSEGS) / 2 + i * (CPT / 2);
#pragma unroll
    for (int j = 0; j < CPT / 2; j++) {
        float4 v = pp[j];
        P[2 * j]     = make_float2(v.x, v.y);
        P[2 * j + 1] = make_float2(v.z, v.w);
    }

    float Br = 0.f, Bi = 0.f;
#pragma unroll
    for (int j = 0; j < CPT; j++) {
        float tr = fmaf(-a.y, Bi, P[j].x);
        float ti = fmaf( a.y, Br, P[j].y);
        Br = fmaf(a.x, Br, tr);
        Bi = fmaf(a.x, Bi, ti);
    }
    sB[i] = make_float2(Br, Bi);

#pragma unroll
    for (int k = 0; k < 8; k++) {
        int off = 1 << k;
        float2 m = g_mkf[n * 8 + k];
        __syncthreads();
        float lr = 0.f, li = 0.f;
        if (i >= off) { float2 tt = sB[i - off]; lr = tt.x; li = tt.y; }
        __syncthreads();
        if (i >= off) {
            float nr = fmaf(m.x, lr, fmaf(-m.y, li, Br));
            float ni = fmaf(m.x, li, fmaf( m.y, lr, Bi));
            Br = nr; Bi = ni;
            sB[i] = make_float2(Br, Bi);
        }
    }
    __syncthreads();

    float Er = 0.f, Ei = 0.f;
    if (i > 0) { float2 tt = sB[i - 1]; Er = tt.x; Ei = tt.y; }
    float4* cp = g_carry4 + (n * NSEGS) / 2 + i * (CPT / 2);
#pragma unroll
    for (int j = 0; j < CPT / 2; j++) {
        float4 o;
        o.x = Er; o.y = Ei;
        {
            float tr = fmaf(-a.y, Ei, P[2 * j].x);
            float ti = fmaf( a.y, Er, P[2 * j].y);
            Er = fmaf(a.x, Er, tr); Ei = fmaf(a.x, Ei, ti);
        }
        o.z = Er; o.w = Ei;
        {
            float tr = fmaf(-a.y, Ei, P[2 * j + 1].x);
            float ti = fmaf( a.y, Er, P[2 * j + 1].y);
            Er = fmaf(a.x, Er, tr); Ei = fmaf(a.x, Ei, ti);
        }
        cp[j] = o;
    }
}

// ---------------- K3: replay + output, 4 modes/thread, float contribs ----------------
// grid = 512 blocks x 128 threads (4 warps -> all SMSPs). Block covers 512 samples (8 segs).
// q = t&15, s = t>>4 (0..7). contrib: 16 float rows (4-mode sums pre-added).
__global__ void k3_apply(const float* __restrict__ u,
                         const float* __restrict__ D,
                         float* __restrict__ y) {
    __shared__ float su[K3_TILE];
    __shared__ float ctb[16][CTB_STRIDE];
    int t = threadIdx.x, tile = blockIdx.x;
    ((float4*)su)[t] = ((const float4*)u)[tile * (K3_TILE / 4) + t];
    int q = t & 15, s = t >> 4;
    int seg = tile * 8 + s;

    float2 za = g_z[q],      zb = g_z[q + 16];
    float2 zc = g_z[q + 32], zd = g_z[q + 48];
    u64t zr0 = pk2(za.x, zb.x), zi0 = pk2(za.y, zb.y), nzi0 = pk2(-za.y, -zb.y);
    u64t zr1 = pk2(zc.x, zd.x), zi1 = pk2(zc.y, zd.y), nzi1 = pk2(-zc.y, -zd.y);
    float2 ca = g_cf[q],      cb = g_cf[q + 16];
    float2 cc = g_cf[q + 32], cd = g_cf[q + 48];
    u64t cr0 = pk2(ca.x, cb.x), nci0 = pk2(-ca.y, -cb.y);
    u64t cr1 = pk2(cc.x, cd.x), nci1 = pk2(-cc.y, -cd.y);

    const float2* gc = (const float2*)g_carry4;
    float2 xa = gc[q * NSEGS + seg],        xb = gc[(q + 16) * NSEGS + seg];
    float2 xc = gc[(q + 32) * NSEGS + seg], xd = gc[(q + 48) * NSEGS + seg];
    u64t Pr0 = pk2(xa.x, xb.x), Pi0 = pk2(xa.y, xb.y);
    u64t Pr1 = pk2(xc.x, xd.x), Pi1 = pk2(xc.y, xd.y);
    __syncthreads();

    const float* up   = su + s * SEG;
    float*       crow = &ctb[q][s * SEG];
#pragma unroll
    for (int j = 0; j < SEG; j++) {
        float uv = up[j];
        u64t u2 = pk2(uv, uv);
        u64t t0, v0, t1, v1, c0, c1, cs;
        FMA2(t0, nzi0, Pi0, u2); MUL2(v0, zi0, Pr0);
        FMA2(Pr0, zr0, Pr0, t0); FMA2(Pi0, zr0, Pi0, v0);
        FMA2(t1, nzi1, Pi1, u2); MUL2(v1, zi1, Pr1);
        FMA2(Pr1, zr1, Pr1, t1); FMA2(Pi1, zr1, Pi1, v1);
        MUL2(c0, nci0, Pi0); FMA2(c0, cr0, Pr0, c0);
        MUL2(c1, nci1, Pi1); FMA2(c1, cr1, Pr1, c1);
        ADD2(cs, c0, c1);
        float lo, hi; upk2(lo, hi, cs);
        crow[j] = lo + hi;           // 4-mode partial sum, single float
    }
    __syncthreads();

    float Dv = D[0];
#pragma unroll
    for (int k = 0; k < 4; k++) {
        int col = t + k * K3_THR;    // strided: conflict-free reads
        float acc = ctb[0][col];
#pragma unroll
        for (int r = 1; r < 16; r++) acc += ctb[r][col];
        y[tile * K3_TILE + col] = fmaf(Dv, su[col], acc);
    }
}

// ---------------- host ----------------
extern "C" void kernel_launch(void* const* d_in, const int* in_sizes, int n_in,
                              void* d_out, int out_size) {
    const float* u = 0; const float* A_re = 0; const float* A_im = 0;
    const float* C = 0; const float* D = 0; const float* log_step = 0;
    for (int i = 0; i < n_in; i++) {
        int sz = in_sizes[i];
        const float* p = (const float*)d_in[i];
        if (sz == LSEQ)            { if (!u) u = p; }
        else if (sz == 2 * NMODES) { if (!C) C = p; }
        else if (sz == NMODES)     { if (!A_re) A_re = p; else A_im = p; }
        else if (sz == 1)          { if (!D) D = p; else log_step = p; }
    }
    float* y = (float*)d_out;

    k0_setup<<<1, NMODES>>>(A_re, A_im, C, log_step);
    k1_partials<<<K1_BLOCKS, K1_THR>>>(u);
    k2_scan<<<NMODES, SCAN_T>>>();
    k3_apply<<<K3_BLOCKS, K3_THR>>>(u, D, y);
}